// round 17
// baseline (speedup 1.0000x reference)
#include <cuda_runtime.h>
#include <cuda_bf16.h>
#include <cstdint>

// ---------------------------------------------------------------------------
// RnnTfModel: k_embproj (exact R1) + fused LSTM/head.
// R17 = R15 + row-group pipelining:
//   batch rows split A={0,1}, B={2,3} (independent recurrences).
//   Each phase (ONE barrier): matvec(group gm=p&1) || combine(other group).
//   Combine latency now hides under the other group's FMA stream.
//   Matvec tiling, combine math, numerics = R15 exactly.
// B=512, T=1024, D=H=64, 4H=256, V=8193. 128 blocks x 512 threads.
// ---------------------------------------------------------------------------

#define B_   512
#define T_   1024
#define D_   64
#define G4_  256
#define V_   8193
#define NB_  4
#define NBLK_ 128
#define THR_ 512

using ull = unsigned long long;

__device__ float g_table[V_ * G4_];      // projected embedding table (8.4 MB)

__device__ __forceinline__ void ffma2(ull& d, ull a, ull b) {
    asm("fma.rn.f32x2 %0, %1, %2, %0;" : "+l"(d) : "l"(a), "l"(b));
}
__device__ __forceinline__ float2 unpack2(ull v) {
    float2 f;
    asm("mov.b64 {%0, %1}, %2;" : "=f"(f.x), "=f"(f.y) : "l"(v));
    return f;
}
__device__ __forceinline__ ull pack2(float lo, float hi) {
    ull v;
    asm("mov.b64 %0, {%1, %2};" : "=l"(v) : "f"(lo), "f"(hi));
    return v;
}
__device__ __forceinline__ float sigm_(float x) {
    return 1.0f / (1.0f + __expf(-x));
}
__device__ __forceinline__ float tanh_(float x) {
    float e = __expf(-2.0f * x);
    return (1.0f - e) / (1.0f + e);
}

// ---------------------------------------------------------------------------
// Kernel 1: projected embedding table — EXACT R1 code.
// ---------------------------------------------------------------------------
__global__ void k_embproj(const float* __restrict__ emb,
                          const float* __restrict__ W1,
                          const float* __restrict__ b1) {
    int v = blockIdx.x;
    int j = threadIdx.x;
    __shared__ float e[D_];
    if (j < D_) e[j] = emb[v * D_ + j];
    __syncthreads();
    float acc = b1[j];
#pragma unroll
    for (int k = 0; k < D_; k++) acc += e[k] * __ldg(&W1[k * G4_ + j]);
    g_table[v * G4_ + j] = acc;
}

// ---------------------------------------------------------------------------
// Kernel 2: fused LSTM + head, 512 threads, row-group pipelined.
// matvec role: thread (ke = j>>6 in [0,8), jq = j&63) -> cols 4jq..4jq+3.
//   z2: stacked [h1; h2] rows [16ke,16ke+16).  z1: U1 rows [8ke,8ke+8).
// combine role: lay = j>>8 (0: h2, 1: h1), rc = (j>>6)&3, uc = j&63.
//   Fires in phase p iff (rc>>1) == gc, gc = 1-(p&1).
// Dynamic smem (floats):
//   [0,256) hc1[4][64] (single buffer); [256,512) hc2[4][64];
//   [512,8704) zp1[8][4][256]; [8704,16896) zp2[8][4][256];
//   [16896,20992) code_s; [20992,21256) zbn; [21256,21384) hid
// ---------------------------------------------------------------------------
#define SM_HC1   0
#define SM_HC2   256
#define SM_ZP1   512
#define SM_ZP2   8704
#define SM_CODE  16896
#define SM_ZBN   20992
#define SM_HID   21256
#define SMEM_BYTES (21384 * 4)

__global__ void __launch_bounds__(THR_, 1)
k_main(const int* __restrict__ code_in,
       const float* __restrict__ U1,
       const float* __restrict__ W2,
       const float* __restrict__ U2,
       const float* __restrict__ b2,
       const float* __restrict__ aux,
       const float* __restrict__ Wlm, const float* __restrict__ blm,
       const float* __restrict__ gamma, const float* __restrict__ beta,
       const float* __restrict__ mean, const float* __restrict__ var,
       const float* __restrict__ W3, const float* __restrict__ b3,
       const float* __restrict__ W4, const float* __restrict__ b4,
       float* __restrict__ out) {
    extern __shared__ __align__(16) float smem[];
    float* hc1   = smem + SM_HC1;    // h1[r][u], single buffer
    float* hc2   = smem + SM_HC2;    // h2[r][u], single buffer
    float* zp1   = smem + SM_ZP1;    // [ke][r][col]
    float* zp2   = smem + SM_ZP2;
    int*   code_s = (int*)(smem + SM_CODE);
    float* zbn   = smem + SM_ZBN;
    float* hid   = smem + SM_HID;

    const int j   = threadIdx.x;
    const int ke  = j >> 6;          // k-eighth (warp-uniform)
    const int jq  = j & 63;
    const int c0  = 4 * jq;
    const int lay = j >> 8;          // combine layer: 0 -> h2, 1 -> h1
    const int rc  = (j >> 6) & 3;    // combine row
    const int uc  = j & 63;          // combine unit
    const int b0  = blockIdx.x * NB_;

    // ---- z2 weights: stacked [W2;U2] rows [16ke,16ke+16) x cols c0..c0+3 ----
    const float* M2 = (ke < 4) ? W2 : U2;
    const int kr0 = 16 * (ke & 3);
    ull w2[4][8];
#pragma unroll
    for (int c = 0; c < 4; c++)
#pragma unroll
        for (int p = 0; p < 8; p++) {
            int k = kr0 + 2 * p;
            w2[c][p] = pack2(__ldg(&M2[k * G4_ + c0 + c]),
                             __ldg(&M2[(k + 1) * G4_ + c0 + c]));
        }
    // ---- z1 weights: U1 rows [8ke,8ke+8) x cols c0..c0+3 ----
    ull w1[4][4];
#pragma unroll
    for (int c = 0; c < 4; c++)
#pragma unroll
        for (int p = 0; p < 4; p++) {
            int k = 8 * ke + 2 * p;
            w1[c][p] = pack2(__ldg(&U1[k * G4_ + c0 + c]),
                             __ldg(&U1[(k + 1) * G4_ + c0 + c]));
        }

    // combine-role constants
    float4 b2c = make_float4(0.f, 0.f, 0.f, 0.f);
    if (lay == 0) {
        b2c.x = __ldg(&b2[uc]);
        b2c.y = __ldg(&b2[64 + uc]);
        b2c.z = __ldg(&b2[128 + uc]);
        b2c.w = __ldg(&b2[192 + uc]);
    }

    for (int i = j; i < NB_ * T_; i += THR_) {
        int r = i >> 10, t = i & (T_ - 1);
        code_s[i] = code_in[(b0 + r) * T_ + t];
    }
    if (j < 256) { hc1[j] = 0.0f; hc2[j] = 0.0f; }
    __syncthreads();

    float c1 = 0.0f, c2 = 0.0f;
    float4 cur = make_float4(0.f, 0.f, 0.f, 0.f);

    // ---- prologue (lay==1 threads): h1_0 = f(x_0) for ALL rows; cur = x_1 ----
    if (lay == 1) {
        const float* row0 = &g_table[(size_t)code_s[rc * T_] * G4_];
        float iv = sigm_(__ldg(&row0[uc]));
        float gv = tanh_(__ldg(&row0[128 + uc]));
        float ov = sigm_(__ldg(&row0[192 + uc]));
        c1 = iv * gv;
        hc1[rc * 64 + uc] = ov * tanh_(c1);             // h1_0
        const float* row1 = &g_table[(size_t)code_s[rc * T_ + 1] * G4_];
        cur.x = __ldg(&row1[uc]);
        cur.y = __ldg(&row1[64 + uc]);
        cur.z = __ldg(&row1[128 + uc]);
        cur.w = __ldg(&row1[192 + uc]);
    }
    __syncthreads();   // h1_0 visible

    // ====================== phase loop: 2T+1 phases ========================
    // phase p: matvec group gm=p&1 at step s=p>>1 (if p<2T);
    //          combine group gc=1-gm at step s_c=(p-1)>>1 (if p>=1).
    for (int p = 0; p <= 2 * T_; p++) {
        const int gm = p & 1;
        const int gc = 1 - gm;
        const bool do_mv = (p < 2 * T_);
        const bool my_cb = (p > 0) && ((rc >> 1) == gc);
        const int r0 = 2 * gm;

        // ---- combine (other group): h2_{s_c} (lay0) / h1_{s_c+1} (lay1) ----
        // Reads zp written last phase; writes h rows gc (disjoint from matvec
        // reads of rows gm this phase).
        float4 nxt = make_float4(0.f, 0.f, 0.f, 0.f);
        if (my_cb) {
            if (lay == 0) {
                float z0 = b2c.x, z1g = b2c.y, z2g = b2c.z, z3 = b2c.w;
#pragma unroll
                for (int q = 0; q < 8; q++) {
                    z0  += zp2[q * 1024 + rc * G4_ + uc];
                    z1g += zp2[q * 1024 + rc * G4_ + 64 + uc];
                    z2g += zp2[q * 1024 + rc * G4_ + 128 + uc];
                    z3  += zp2[q * 1024 + rc * G4_ + 192 + uc];
                }
                float iv = sigm_(z0), fv = sigm_(z1g);
                float gv = tanh_(z2g), ov = sigm_(z3);
                c2 = fv * c2 + iv * gv;
                hc2[rc * 64 + uc] = ov * tanh_(c2);     // h2_{s_c}
            } else {
                // prefetch x_{s_c+2} for the next firing (2 phases away)
                int sc = (p - 1) >> 1;
                int tn = (sc + 2 < T_) ? (sc + 2) : (T_ - 1);
                const float* row = &g_table[(size_t)code_s[rc * T_ + tn] * G4_];
                nxt.x = __ldg(&row[uc]);
                nxt.y = __ldg(&row[64 + uc]);
                nxt.z = __ldg(&row[128 + uc]);
                nxt.w = __ldg(&row[192 + uc]);

                float y0 = cur.x, y1 = cur.y, y2 = cur.z, y3 = cur.w;
#pragma unroll
                for (int q = 0; q < 8; q++) {
                    y0 += zp1[q * 1024 + rc * G4_ + uc];
                    y1 += zp1[q * 1024 + rc * G4_ + 64 + uc];
                    y2 += zp1[q * 1024 + rc * G4_ + 128 + uc];
                    y3 += zp1[q * 1024 + rc * G4_ + 192 + uc];
                }
                float iv = sigm_(y0), fv = sigm_(y1);
                float gv = tanh_(y2), ov = sigm_(y3);
                c1 = fv * c1 + iv * gv;
                hc1[rc * 64 + uc] = ov * tanh_(c1);     // h1_{s_c+1}
            }
        }

        // ---- matvec (group gm, rows r0, r0+1) ----
        if (do_mv) {
            const float* kb = (ke < 4) ? hc1 : hc2;
            // z2(s) partials: 16 stacked k-rows, 2 rows
#pragma unroll
            for (int rr = 0; rr < 2; rr++) {
                const int r = r0 + rr;
                ull acc[4] = {0, 0, 0, 0};
#pragma unroll
                for (int i = 0; i < 4; i++) {
                    ulonglong2 hv = *(const ulonglong2*)
                        &kb[r * 64 + kr0 + 4 * i];
#pragma unroll
                    for (int c = 0; c < 4; c++) {
                        ffma2(acc[c], hv.x, w2[c][2 * i]);
                        ffma2(acc[c], hv.y, w2[c][2 * i + 1]);
                    }
                }
                float2 p0 = unpack2(acc[0]), p1 = unpack2(acc[1]);
                float2 p2 = unpack2(acc[2]), p3 = unpack2(acc[3]);
                *(float4*)&zp2[ke * 1024 + r * G4_ + c0] =
                    make_float4(p0.x + p0.y, p1.x + p1.y,
                                p2.x + p2.y, p3.x + p3.y);
            }
            // z1(s+1) partials: 8 U1 k-rows vs h1_s, 2 rows
#pragma unroll
            for (int rr = 0; rr < 2; rr++) {
                const int r = r0 + rr;
                ull acc[4] = {0, 0, 0, 0};
#pragma unroll
                for (int i = 0; i < 2; i++) {
                    ulonglong2 hv = *(const ulonglong2*)
                        &hc1[r * 64 + 8 * ke + 4 * i];
#pragma unroll
                    for (int c = 0; c < 4; c++) {
                        ffma2(acc[c], hv.x, w1[c][2 * i]);
                        ffma2(acc[c], hv.y, w1[c][2 * i + 1]);
                    }
                }
                float2 p0 = unpack2(acc[0]), p1 = unpack2(acc[1]);
                float2 p2 = unpack2(acc[2]), p3 = unpack2(acc[3]);
                *(float4*)&zp1[ke * 1024 + r * G4_ + c0] =
                    make_float4(p0.x + p0.y, p1.x + p1.y,
                                p2.x + p2.y, p3.x + p3.y);
            }
        }

        if (my_cb && lay == 1) cur = nxt;

        __syncthreads();   // end of phase: zp + h publishes visible
    }

    // final h2 in hc2 rows 0-3
    // ============================ head (4 rows) ============================
    if (j < 264) {
        int r = j / 66, k = j % 66;
        float v = (k < 2) ? aux[(b0 + r) * 2 + k] : hc2[r * 64 + (k - 2)];
        zbn[r * 66 + k] =
            gamma[k] * (v - mean[k]) * rsqrtf(var[k] + 1e-3f) + beta[k];
    }
    __syncthreads();
    if (j < 128) {
        int r = j >> 5, i = j & 31;
        float acc = b3[i];
#pragma unroll
        for (int k = 0; k < 66; k++)
            acc += zbn[r * 66 + k] * __ldg(&W3[k * 32 + i]);
        hid[r * 32 + i] = fmaxf(acc, 0.0f);
    }
    __syncthreads();
    if (j < NB_) {
        int r = j;
        float o0 = b4[0], o1 = b4[1];
#pragma unroll
        for (int k = 0; k < 32; k++) {
            o0 += hid[r * 32 + k] * __ldg(&W4[k * 2 + 0]);
            o1 += hid[r * 32 + k] * __ldg(&W4[k * 2 + 1]);
        }
        float m = fmaxf(o0, o1);
        float e0 = __expf(o0 - m), e1 = __expf(o1 - m);
        float inv = 1.0f / (e0 + e1);
        out[(b0 + r) * 2 + 0] = e0 * inv;
        out[(b0 + r) * 2 + 1] = e1 * inv;

        float l0 = blm[0], l1 = blm[1];
#pragma unroll
        for (int k = 0; k < 64; k++) {
            float h = hc2[r * 64 + k];
            l0 += h * __ldg(&Wlm[k * 2 + 0]);
            l1 += h * __ldg(&Wlm[k * 2 + 1]);
        }
        out[B_ * 2 + (b0 + r) * 2 + 0] = sigm_(l0);
        out[B_ * 2 + (b0 + r) * 2 + 1] = sigm_(l1);
    }
}

// ---------------------------------------------------------------------------
// launcher
// inputs: 0 aux_in, 1 code_in, 2 emb, 3 W1, 4 U1, 5 b1, 6 W2, 7 U2, 8 b2,
//         9 Wlm, 10 blm, 11 bn_gamma, 12 bn_beta, 13 bn_mean, 14 bn_var,
//         15 W3, 16 b3, 17 W4, 18 b4
// ---------------------------------------------------------------------------
extern "C" void kernel_launch(void* const* d_in, const int* in_sizes, int n_in,
                              void* d_out, int out_size) {
    const float* aux   = (const float*)d_in[0];
    const int*   code  = (const int*)d_in[1];
    const float* emb   = (const float*)d_in[2];
    const float* W1    = (const float*)d_in[3];
    const float* U1    = (const float*)d_in[4];
    const float* b1    = (const float*)d_in[5];
    const float* W2    = (const float*)d_in[6];
    const float* U2    = (const float*)d_in[7];
    const float* b2    = (const float*)d_in[8];
    const float* Wlm   = (const float*)d_in[9];
    const float* blm   = (const float*)d_in[10];
    const float* gamma = (const float*)d_in[11];
    const float* beta  = (const float*)d_in[12];
    const float* mean  = (const float*)d_in[13];
    const float* var   = (const float*)d_in[14];
    const float* W3    = (const float*)d_in[15];
    const float* b3    = (const float*)d_in[16];
    const float* W4    = (const float*)d_in[17];
    const float* b4    = (const float*)d_in[18];
    float* out = (float*)d_out;

    cudaFuncSetAttribute(k_main, cudaFuncAttributeMaxDynamicSharedMemorySize,
                         SMEM_BYTES);

    k_embproj<<<V_, 256>>>(emb, W1, b1);
    k_main<<<NBLK_, THR_, SMEM_BYTES>>>(code, U1, W2, U2, b2,
                                        aux, Wlm, blm, gamma, beta, mean, var,
                                        W3, b3, W4, b4, out);
}